// round 13
// baseline (speedup 1.0000x reference)
#include <cuda_runtime.h>
#include <cuda_fp16.h>
#include <cstdint>

#define KN 131072
#define KK 16
#define KM 128
#define KD 64
#define BN 128   // n-rows per CTA (4 producer warp-pairs x 32 rows)

#define LOG2E 1.4426950408889634f
#define LN2   0.6931471805599453f

// Per-expert tile (16896 B): [0,16384) fp16 'a' fragments (log2e-scaled),
//   one uint4 per (ks, m-tile-pair, lane); [16384,16896): bias*log2e (128 f32)
#define TILE_BYTES 16896
#define TILE_U4    (TILE_BYTES / 16)       // 1056
__device__ __align__(16) unsigned char g_bt[KK * TILE_BYTES];   // 264 KB, L2-resident
__device__ float g_ss[KK];                                      // s * ln2

__global__ void prep(const float* __restrict__ a, const float* __restrict__ b,
                     const float* __restrict__ s) {
    int idx = blockIdx.x * 256 + threadIdx.x;
    if (idx < 65536) {
        int c  = idx & 3;
        int l  = (idx >> 2) & 31;
        int mp = (idx >> 7) & 7;
        int ks = (idx >> 10) & 3;
        int k  = idx >> 12;
        int mt = mp * 2 + (c >> 1);
        int r  = c & 1;
        int m  = mt * 8 + (l >> 2);
        int d0 = ks * 16 + (l & 3) * 2 + r * 8;
        const float* am = a + ((size_t)k * KM + m) * KD + d0;
        __half2 h = __floats2half2_rn(am[0] * LOG2E, am[1] * LOG2E);
        *(uint32_t*)(g_bt + (size_t)k * TILE_BYTES +
                     ((((ks * 8 + mp) * 32 + l) * 4 + c) << 2)) = *(const uint32_t*)&h;
    } else if (idx < 65536 + KK * KM) {
        int j = idx - 65536;
        int k = j >> 7, m = j & 127;
        *(float*)(g_bt + (size_t)k * TILE_BYTES + 16384 + (m << 2)) = b[j] * LOG2E;
        if (j < KK) g_ss[j] = s[j] * LN2;
    }
}

__device__ __forceinline__ void mma16816(float (&c)[4], const uint32_t (&A)[4],
                                         uint32_t b0, uint32_t b1) {
    asm volatile(
        "mma.sync.aligned.m16n8k16.row.col.f32.f16.f16.f32 "
        "{%0,%1,%2,%3}, {%4,%5,%6,%7}, {%8,%9}, {%0,%1,%2,%3};"
        : "+f"(c[0]), "+f"(c[1]), "+f"(c[2]), "+f"(c[3])
        : "r"(A[0]), "r"(A[1]), "r"(A[2]), "r"(A[3]), "r"(b0), "r"(b1));
}
__device__ __forceinline__ uint32_t smem_u32(const void* p) {
    uint32_t a;
    asm("{ .reg .u64 t; cvta.to.shared.u64 t, %1; cvt.u32.u64 %0, t; }" : "=r"(a) : "l"(p));
    return a;
}
__device__ __forceinline__ void cp16(uint32_t s, const void* g) {
    asm volatile("cp.async.cg.shared.global [%0], [%1], 16;" :: "r"(s), "l"(g));
}
#define CP_COMMIT() asm volatile("cp.async.commit_group;" ::: "memory")
#define CP_WAIT(n)  asm volatile("cp.async.wait_group %0;" :: "n"(n) : "memory")
__device__ __forceinline__ float ex2f(float v) {
    float r; asm("ex2.approx.f32 %0, %1;" : "=f"(r) : "f"(v)); return r;
}
__device__ __forceinline__ float lg2f(float v) {
    float r; asm("lg2.approx.f32 %0, %1;" : "=f"(r) : "f"(v)); return r;
}
__device__ __forceinline__ uint32_t packh(float a, float b) {
    __half2 h = __floats2half2_rn(a, b);
    return *(const uint32_t*)&h;
}

// ---- mbarrier helpers (base-arch legal; arrive=release, try_wait=acquire) ----
#define MBAR_INIT(addr, cnt) \
    asm volatile("mbarrier.init.shared.b64 [%0], %1;" :: "r"((uint32_t)(addr)), "r"((uint32_t)(cnt)) : "memory")
#define MBAR_ARRIVE(addr) \
    asm volatile("mbarrier.arrive.shared.b64 _, [%0];" :: "r"((uint32_t)(addr)) : "memory")
#define MBAR_WAIT(addr, ph) do { \
    uint32_t _m = (uint32_t)(addr), _p = (uint32_t)(ph), _d; \
    asm volatile("{\n\t.reg .pred p;\n\t" \
        "mbarrier.try_wait.parity.acquire.cta.shared::cta.b64 p, [%1], %2;\n\t" \
        "selp.b32 %0, 1, 0, p;\n\t}" : "=r"(_d) : "r"(_m), "r"(_p) : "memory"); \
    if (!_d) { \
        asm volatile("{\n\t.reg .pred P1;\n\t" \
            "W_%=:\n\t" \
            "mbarrier.try_wait.parity.acquire.cta.shared::cta.b64 P1, [%0], %1, 0x989680;\n\t" \
            "@P1 bra.uni D_%=;\n\t" \
            "bra.uni W_%=;\n\t" \
            "D_%=:\n\t}" :: "r"(_m), "r"(_p) : "memory"); \
    } \
} while (0)

// SMEM layout (bytes):
// [0, 33792)           : 2 a-tile buffers
// [33792, 66560)       : score buffers, pair p buf d at 33792 + (p*2+d)*4096
// [66560, 66560+17*8)  : mbarriers: full[p][d]=p*2+d, empty[p][d]=8+p*2+d, tile=16
#define SCORE_OFF 33792
#define MBAR_OFF  66560
#define DYN_SMEM  (MBAR_OFF + 17 * 8)

__global__ __launch_bounds__(256, 2)
void madk12(const float* __restrict__ x, float* __restrict__ out)
{
    extern __shared__ __align__(16) char smem[];
    const uint32_t sb = smem_u32(smem);
    const int tid = threadIdx.x;
    const int w = tid >> 5, l = tid & 31;
    const int g = l >> 2, q = l & 3;

    // ---- init 17 mbarriers, then the only CTA-wide sync in the kernel ----
    if (tid == 0) {
        #pragma unroll
        for (int i = 0; i < 16; ++i) MBAR_INIT(sb + MBAR_OFF + i * 8, 32);
        MBAR_INIT(sb + MBAR_OFF + 16 * 8, 128);
    }
    __syncthreads();

    if (w < 4) {
        // ================= PRODUCER (MMA) =================
        const int pair = w;
        const int row0 = blockIdx.x * BN + pair * 32 + g;

        // prefetch expert 0 (producers = threads 0..127 own the tile pipeline)
        {
            uint32_t dst = sb;
            const char* src = (const char*)g_bt;
            #pragma unroll
            for (int i = 0; i < 9; ++i) {
                int o = tid + i * 128;
                if (o < TILE_U4) cp16(dst + o * 16, src + o * 16);
            }
            CP_COMMIT();
        }

        // A fragments: two 16-row fragments, fp16, reused for all experts
        uint32_t X[2][4][4];
        #pragma unroll
        for (int p = 0; p < 2; ++p) {
            #pragma unroll
            for (int ks = 0; ks < 4; ++ks) {
                #pragma unroll
                for (int h = 0; h < 2; ++h) {
                    int d = ks * 16 + q * 2 + h * 8;
                    int r = row0 + p * 16;
                    float2 v0 = __ldg((const float2*)(x + (size_t)r * KD + d));
                    float2 v1 = __ldg((const float2*)(x + (size_t)(r + 8) * KD + d));
                    X[p][ks][h * 2 + 0] = packh(v0.x, v0.y);
                    X[p][ks][h * 2 + 1] = packh(v1.x, v1.y);
                }
            }
        }

        int cc = 0;
        #pragma unroll 1
        for (int k = 0; k < KK; ++k) {
            CP_WAIT(0);
            // producers-only tile barrier (128 arrivals): everyone is past
            // reading the buffer the next cp.async will overwrite
            MBAR_ARRIVE(sb + MBAR_OFF + 16 * 8);
            MBAR_WAIT(sb + MBAR_OFF + 16 * 8, k & 1);

            if (k + 1 < KK) {
                uint32_t dst = sb + ((k + 1) & 1) * (TILE_U4 * 16);
                const char* src = (const char*)(g_bt + (size_t)(k + 1) * TILE_BYTES);
                #pragma unroll
                for (int i = 0; i < 9; ++i) {
                    int o = tid + i * 128;
                    if (o < TILE_U4) cp16(dst + o * 16, src + o * 16);
                }
                CP_COMMIT();
            }

            const uint4* abv = (const uint4*)(smem + (k & 1) * (TILE_U4 * 16)) + l;
            const float2* bv = (const float2*)(smem + (k & 1) * (TILE_U4 * 16) + 16384) + q;

            #pragma unroll
            for (int ch = 0; ch < 4; ++ch) {
                float acc0[4][4], acc1[4][4];
                #pragma unroll
                for (int mt = 0; mt < 4; ++mt) {
                    float2 bb = bv[(ch * 4 + mt) * 4];
                    acc0[mt][0] = bb.x; acc0[mt][1] = bb.y;
                    acc0[mt][2] = bb.x; acc0[mt][3] = bb.y;
                    acc1[mt][0] = bb.x; acc1[mt][1] = bb.y;
                    acc1[mt][2] = bb.x; acc1[mt][3] = bb.y;
                }

                uint4 B[4][2];
                #pragma unroll
                for (int ks = 0; ks < 4; ++ks)
                    #pragma unroll
                    for (int mp = 0; mp < 2; ++mp)
                        B[ks][mp] = abv[(ks * 8 + ch * 2 + mp) * 32];

                #pragma unroll
                for (int ks = 0; ks < 4; ++ks) {
                    #pragma unroll
                    for (int mp = 0; mp < 2; ++mp) {
                        mma16816(acc0[mp * 2 + 0], X[0][ks], B[ks][mp].x, B[ks][mp].y);
                        mma16816(acc1[mp * 2 + 0], X[1][ks], B[ks][mp].x, B[ks][mp].y);
                        mma16816(acc0[mp * 2 + 1], X[0][ks], B[ks][mp].z, B[ks][mp].w);
                        mma16816(acc1[mp * 2 + 1], X[1][ks], B[ks][mp].z, B[ks][mp].w);
                    }
                }

                // hand off scores to the consumer warp of this pair
                int d = cc & 1;
                if (cc >= 2) MBAR_WAIT(sb + MBAR_OFF + (8 + pair * 2 + d) * 8, ((cc - 2) >> 1) & 1);
                float4* sc = (float4*)(smem + SCORE_OFF + (pair * 2 + d) * 4096) + l;
                #pragma unroll
                for (int mt = 0; mt < 4; ++mt) {
                    sc[mt * 32]       = make_float4(acc0[mt][0], acc0[mt][1], acc0[mt][2], acc0[mt][3]);
                    sc[(4 + mt) * 32] = make_float4(acc1[mt][0], acc1[mt][1], acc1[mt][2], acc1[mt][3]);
                }
                MBAR_ARRIVE(sb + MBAR_OFF + (pair * 2 + d) * 8);   // full (release)
                ++cc;
            }
        }
    } else {
        // ================= CONSUMER (exp / lse) =================
        const int pair = w - 4;
        const int row0 = blockIdx.x * BN + pair * 32 + g;
        float res0 = 0.f, res1 = 0.f, res2 = 0.f, res3 = 0.f;
        int cc = 0;

        #pragma unroll 1
        for (int k = 0; k < KK; ++k) {
            float s0 = 0.f, s1 = 0.f, s2 = 0.f, s3 = 0.f;
            #pragma unroll
            for (int ch = 0; ch < 4; ++ch) {
                int d = cc & 1;
                MBAR_WAIT(sb + MBAR_OFF + (pair * 2 + d) * 8, (cc >> 1) & 1);  // full (acquire)
                const float4* sc = (const float4*)(smem + SCORE_OFF + (pair * 2 + d) * 4096) + l;
                #pragma unroll
                for (int j = 0; j < 4; ++j) {
                    float4 v = sc[j * 32];
                    s0 += ex2f(v.x); s0 += ex2f(v.y);
                    s1 += ex2f(v.z); s1 += ex2f(v.w);
                }
                #pragma unroll
                for (int j = 4; j < 8; ++j) {
                    float4 v = sc[j * 32];
                    s2 += ex2f(v.x); s2 += ex2f(v.y);
                    s3 += ex2f(v.z); s3 += ex2f(v.w);
                }
                MBAR_ARRIVE(sb + MBAR_OFF + (8 + pair * 2 + d) * 8);  // empty (release)
                ++cc;
            }

            s0 += __shfl_xor_sync(0xffffffffu, s0, 1);
            s0 += __shfl_xor_sync(0xffffffffu, s0, 2);
            s1 += __shfl_xor_sync(0xffffffffu, s1, 1);
            s1 += __shfl_xor_sync(0xffffffffu, s1, 2);
            s2 += __shfl_xor_sync(0xffffffffu, s2, 1);
            s2 += __shfl_xor_sync(0xffffffffu, s2, 2);
            s3 += __shfl_xor_sync(0xffffffffu, s3, 1);
            s3 += __shfl_xor_sync(0xffffffffu, s3, 2);

            float sv = g_ss[k];
            res0 = fmaf(sv, lg2f(s0), res0);
            res1 = fmaf(sv, lg2f(s1), res1);
            res2 = fmaf(sv, lg2f(s2), res2);
            res3 = fmaf(sv, lg2f(s3), res3);
        }

        if (q == 0) {
            out[row0]      = res0;
            out[row0 + 8]  = res1;
            out[row0 + 16] = res2;
            out[row0 + 24] = res3;
        }
    }
}

extern "C" void kernel_launch(void* const* d_in, const int* in_sizes, int n_in,
                              void* d_out, int out_size)
{
    const float* x = (const float*)d_in[0];   // [131072, 64]
    const float* s = (const float*)d_in[1];   // [16]
    const float* a = (const float*)d_in[2];   // [16, 128, 64]
    const float* b = (const float*)d_in[3];   // [16, 128]
    float* out = (float*)d_out;

    cudaFuncSetAttribute(madk12, cudaFuncAttributeMaxDynamicSharedMemorySize, DYN_SMEM);

    prep<<<(65536 + KK * KM + 255) / 256, 256>>>(a, b, s);
    madk12<<<KN / BN, 256, DYN_SMEM>>>(x, out);
}

// round 15
// speedup vs baseline: 2.0278x; 2.0278x over previous
#include <cuda_runtime.h>
#include <cuda_fp16.h>
#include <cstdint>

#define KN 131072
#define KK 16
#define KM 128
#define KD 64
#define BN 64    // n-rows per CTA (4 warps x 16 rows)

#define LOG2E 1.4426950408889634f
#define LN2   0.6931471805599453f

// Per-expert tile (16896 B): [0,16384) fp16 'a' fragments (log2e-scaled),
//   one uint4 per (ks, m-tile-pair, lane); [16384,16896): bias*log2e (128 f32)
#define TILE_BYTES 16896
#define TILE_U4    (TILE_BYTES / 16)       // 1056
__device__ __align__(16) unsigned char g_bt[KK * TILE_BYTES];   // 264 KB, L2-resident
__device__ float g_ss[KK];                                      // s * ln2

__global__ void prep(const float* __restrict__ a, const float* __restrict__ b,
                     const float* __restrict__ s) {
    int idx = blockIdx.x * 256 + threadIdx.x;
    if (idx < 65536) {
        int c  = idx & 3;
        int l  = (idx >> 2) & 31;
        int mp = (idx >> 7) & 7;
        int ks = (idx >> 10) & 3;
        int k  = idx >> 12;
        int mt = mp * 2 + (c >> 1);
        int r  = c & 1;
        int m  = mt * 8 + (l >> 2);
        int d0 = ks * 16 + (l & 3) * 2 + r * 8;
        const float* am = a + ((size_t)k * KM + m) * KD + d0;
        __half2 h = __floats2half2_rn(am[0] * LOG2E, am[1] * LOG2E);
        *(uint32_t*)(g_bt + (size_t)k * TILE_BYTES +
                     ((((ks * 8 + mp) * 32 + l) * 4 + c) << 2)) = *(const uint32_t*)&h;
    } else if (idx < 65536 + KK * KM) {
        int j = idx - 65536;
        int k = j >> 7, m = j & 127;
        *(float*)(g_bt + (size_t)k * TILE_BYTES + 16384 + (m << 2)) = b[j] * LOG2E;
        if (j < KK) g_ss[j] = s[j] * LN2;
    }
}

__device__ __forceinline__ void mma16816(float (&c)[4], const uint32_t (&A)[4],
                                         uint32_t b0, uint32_t b1) {
    asm volatile(
        "mma.sync.aligned.m16n8k16.row.col.f32.f16.f16.f32 "
        "{%0,%1,%2,%3}, {%4,%5,%6,%7}, {%8,%9}, {%0,%1,%2,%3};"
        : "+f"(c[0]), "+f"(c[1]), "+f"(c[2]), "+f"(c[3])
        : "r"(A[0]), "r"(A[1]), "r"(A[2]), "r"(A[3]), "r"(b0), "r"(b1));
}
__device__ __forceinline__ uint32_t smem_u32(const void* p) {
    uint32_t a;
    asm("{ .reg .u64 t; cvta.to.shared.u64 t, %1; cvt.u32.u64 %0, t; }" : "=r"(a) : "l"(p));
    return a;
}
__device__ __forceinline__ void cp16(uint32_t s, const void* g) {
    asm volatile("cp.async.cg.shared.global [%0], [%1], 16;" :: "r"(s), "l"(g));
}
#define CP_COMMIT() asm volatile("cp.async.commit_group;" ::: "memory")
#define CP_WAIT(n)  asm volatile("cp.async.wait_group %0;" :: "n"(n) : "memory")
__device__ __forceinline__ float ex2f(float v) {
    float r; asm("ex2.approx.f32 %0, %1;" : "=f"(r) : "f"(v)); return r;
}
__device__ __forceinline__ float lg2f(float v) {
    float r; asm("lg2.approx.f32 %0, %1;" : "=f"(r) : "f"(v)); return r;
}
__device__ __forceinline__ uint32_t packh(float a, float b) {
    __half2 h = __floats2half2_rn(a, b);
    return *(const uint32_t*)&h;
}

#define DYN_SMEM (2 * TILE_BYTES)   // 33792 B double buffer (x6 CTAs = 203 KB/SM)

// 128 threads = 4 warps x 16 rows; 6 CTAs/SM (24 warps) for latency hiding.
__global__ __launch_bounds__(128, 6)
void madk14(const float* __restrict__ x, float* __restrict__ out)
{
    extern __shared__ __align__(16) uint4 smem4[];

    const int tid = threadIdx.x;
    const int w = tid >> 5, l = tid & 31;
    const int g = l >> 2, q = l & 3;
    const int row0 = blockIdx.x * BN + w * 16 + g;

    // ---- prefetch expert 0 ----
    {
        uint32_t dst = smem_u32(smem4);
        const char* src = (const char*)g_bt;
        #pragma unroll
        for (int i = 0; i < 9; ++i) {
            int o = tid + i * 128;
            if (o < TILE_U4) cp16(dst + o * 16, src + o * 16);
        }
        CP_COMMIT();
    }

    // ---- A fragment: one 16-row fragment; reused for all experts ----
    uint32_t X[4][4];
    #pragma unroll
    for (int ks = 0; ks < 4; ++ks) {
        #pragma unroll
        for (int h = 0; h < 2; ++h) {
            int d = ks * 16 + q * 2 + h * 8;
            float2 v0 = __ldg((const float2*)(x + (size_t)row0 * KD + d));
            float2 v1 = __ldg((const float2*)(x + (size_t)(row0 + 8) * KD + d));
            X[ks][h * 2 + 0] = packh(v0.x, v0.y);
            X[ks][h * 2 + 1] = packh(v1.x, v1.y);
        }
    }

    float res0 = 0.f, res1 = 0.f;

    #pragma unroll 1
    for (int k = 0; k < KK; ++k) {
        CP_WAIT(0);
        __syncthreads();

        if (k + 1 < KK) {
            uint32_t dst = smem_u32(smem4 + ((k + 1) & 1) * TILE_U4);
            const char* src = (const char*)(g_bt + (size_t)(k + 1) * TILE_BYTES);
            #pragma unroll
            for (int i = 0; i < 9; ++i) {
                int o = tid + i * 128;
                if (o < TILE_U4) cp16(dst + o * 16, src + o * 16);
            }
            CP_COMMIT();
        }

        const uint4*  abv = smem4 + (k & 1) * TILE_U4 + l;
        const float2* bv  = (const float2*)(smem4 + (k & 1) * TILE_U4 + 1024) + q;
        float s0 = 0.f, s1 = 0.f;

        #pragma unroll
        for (int ch = 0; ch < 4; ++ch) {
            // bias (log2e-scaled) as initial accumulator
            float acc[4][4];
            #pragma unroll
            for (int mt = 0; mt < 4; ++mt) {
                float2 bb = bv[(ch * 4 + mt) * 4];
                acc[mt][0] = bb.x; acc[mt][1] = bb.y;
                acc[mt][2] = bb.x; acc[mt][3] = bb.y;
            }

            // 8 LDS.128 hoisted: each uint4 = B for an m-tile pair
            uint4 B[4][2];
            #pragma unroll
            for (int ks = 0; ks < 4; ++ks)
                #pragma unroll
                for (int mp = 0; mp < 2; ++mp)
                    B[ks][mp] = abv[(ks * 8 + ch * 2 + mp) * 32];

            #pragma unroll
            for (int ks = 0; ks < 4; ++ks) {
                #pragma unroll
                for (int mp = 0; mp < 2; ++mp) {
                    mma16816(acc[mp * 2 + 0], X[ks], B[ks][mp].x, B[ks][mp].y);
                    mma16816(acc[mp * 2 + 1], X[ks], B[ks][mp].z, B[ks][mp].w);
                }
            }

            // fused epilogue: acc = (x@a + b)*log2e
            #pragma unroll
            for (int mt = 0; mt < 4; ++mt) {
                s0 += ex2f(acc[mt][0]);
                s0 += ex2f(acc[mt][1]);
                s1 += ex2f(acc[mt][2]);
                s1 += ex2f(acc[mt][3]);
            }
        }

        s0 += __shfl_xor_sync(0xffffffffu, s0, 1);
        s0 += __shfl_xor_sync(0xffffffffu, s0, 2);
        s1 += __shfl_xor_sync(0xffffffffu, s1, 1);
        s1 += __shfl_xor_sync(0xffffffffu, s1, 2);

        float sv = g_ss[k];                 // s * ln2
        res0 = fmaf(sv, lg2f(s0), res0);
        res1 = fmaf(sv, lg2f(s1), res1);
    }

    if (q == 0) {
        out[row0]     = res0;
        out[row0 + 8] = res1;
    }
}

extern "C" void kernel_launch(void* const* d_in, const int* in_sizes, int n_in,
                              void* d_out, int out_size)
{
    const float* x = (const float*)d_in[0];   // [131072, 64]
    const float* s = (const float*)d_in[1];   // [16]
    const float* a = (const float*)d_in[2];   // [16, 128, 64]
    const float* b = (const float*)d_in[3];   // [16, 128]
    float* out = (float*)d_out;

    cudaFuncSetAttribute(madk14, cudaFuncAttributeMaxDynamicSharedMemorySize, DYN_SMEM);

    prep<<<(65536 + KK * KM + 255) / 256, 256>>>(a, b, s);
    madk14<<<KN / BN, 128, DYN_SMEM>>>(x, out);
}

// round 16
// speedup vs baseline: 2.1990x; 1.0844x over previous
#include <cuda_runtime.h>
#include <cuda_fp16.h>
#include <cstdint>

#define KN 131072
#define KK 16
#define KM 128
#define KD 64
#define BN 128   // n-rows per CTA (4 warps x 32 rows)

#define LOG2E 1.4426950408889634f
#define LN2   0.6931471805599453f

// Per-expert tile (16896 B): [0,16384) fp16 'a' fragments (log2e-scaled),
//   one uint4 per (ks, m-tile-pair, lane); [16384,16896): bias*log2e (128 f32)
#define TILE_BYTES 16896
#define TILE_U4    (TILE_BYTES / 16)       // 1056
__device__ __align__(16) unsigned char g_bt[KK * TILE_BYTES];   // 264 KB, L2-resident
__device__ float g_ss[KK];                                      // s * ln2

__global__ void prep(const float* __restrict__ a, const float* __restrict__ b,
                     const float* __restrict__ s) {
    int idx = blockIdx.x * 256 + threadIdx.x;
    if (idx < 65536) {
        int c  = idx & 3;
        int l  = (idx >> 2) & 31;
        int mp = (idx >> 7) & 7;
        int ks = (idx >> 10) & 3;
        int k  = idx >> 12;
        int mt = mp * 2 + (c >> 1);
        int r  = c & 1;
        int m  = mt * 8 + (l >> 2);
        int d0 = ks * 16 + (l & 3) * 2 + r * 8;
        const float* am = a + ((size_t)k * KM + m) * KD + d0;
        __half2 h = __floats2half2_rn(am[0] * LOG2E, am[1] * LOG2E);
        *(uint32_t*)(g_bt + (size_t)k * TILE_BYTES +
                     ((((ks * 8 + mp) * 32 + l) * 4 + c) << 2)) = *(const uint32_t*)&h;
    } else if (idx < 65536 + KK * KM) {
        int j = idx - 65536;
        int k = j >> 7, m = j & 127;
        *(float*)(g_bt + (size_t)k * TILE_BYTES + 16384 + (m << 2)) = b[j] * LOG2E;
        if (j < KK) g_ss[j] = s[j] * LN2;
    }
}

__device__ __forceinline__ void mma16816(float (&c)[4], const uint32_t (&A)[4],
                                         uint32_t b0, uint32_t b1) {
    asm volatile(
        "mma.sync.aligned.m16n8k16.row.col.f32.f16.f16.f32 "
        "{%0,%1,%2,%3}, {%4,%5,%6,%7}, {%8,%9}, {%0,%1,%2,%3};"
        : "+f"(c[0]), "+f"(c[1]), "+f"(c[2]), "+f"(c[3])
        : "r"(A[0]), "r"(A[1]), "r"(A[2]), "r"(A[3]), "r"(b0), "r"(b1));
}
__device__ __forceinline__ uint32_t smem_u32(const void* p) {
    uint32_t a;
    asm("{ .reg .u64 t; cvta.to.shared.u64 t, %1; cvt.u32.u64 %0, t; }" : "=r"(a) : "l"(p));
    return a;
}
__device__ __forceinline__ void cp16(uint32_t s, const void* g) {
    asm volatile("cp.async.cg.shared.global [%0], [%1], 16;" :: "r"(s), "l"(g));
}
#define CP_COMMIT() asm volatile("cp.async.commit_group;" ::: "memory")
#define CP_WAIT(n)  asm volatile("cp.async.wait_group %0;" :: "n"(n) : "memory")
__device__ __forceinline__ float ex2f(float v) {
    float r; asm("ex2.approx.f32 %0, %1;" : "=f"(r) : "f"(v)); return r;
}
__device__ __forceinline__ float lg2f(float v) {
    float r; asm("lg2.approx.f32 %0, %1;" : "=f"(r) : "f"(v)); return r;
}
__device__ __forceinline__ uint32_t packh(float a, float b) {
    __half2 h = __floats2half2_rn(a, b);
    return *(const uint32_t*)&h;
}

#define DYN_SMEM (2 * TILE_BYTES)   // 33792 B double buffer (x5 CTAs = 169 KB/SM)

// 128 threads = 4 warps x 32 rows; 5 CTAs/SM (20 warps) and 8 independent
// exp-accumulator chains so epilogue warps can keep the issue slots full.
__global__ __launch_bounds__(128, 5)
void madk15(const float* __restrict__ x, float* __restrict__ out)
{
    extern __shared__ __align__(16) uint4 smem4[];

    const int tid = threadIdx.x;
    const int w = tid >> 5, l = tid & 31;
    const int g = l >> 2, q = l & 3;
    const int row0 = blockIdx.x * BN + w * 32 + g;

    // ---- prefetch expert 0 (1024 a-u4 + 32 bias-u4) ----
    {
        uint32_t dst = smem_u32(smem4);
        const char* src = (const char*)g_bt;
        #pragma unroll
        for (int i = 0; i < 8; ++i) {
            int o = tid + i * 128;
            cp16(dst + o * 16, src + o * 16);
        }
        if (tid < 32) cp16(dst + (1024 + tid) * 16, src + (1024 + tid) * 16);
        CP_COMMIT();
    }

    // ---- A fragments: two 16-row fragments; reused for all experts ----
    uint32_t X[2][4][4];
    #pragma unroll
    for (int p = 0; p < 2; ++p) {
        #pragma unroll
        for (int ks = 0; ks < 4; ++ks) {
            #pragma unroll
            for (int h = 0; h < 2; ++h) {
                int d = ks * 16 + q * 2 + h * 8;
                int r = row0 + p * 16;
                float2 v0 = __ldg((const float2*)(x + (size_t)r * KD + d));
                float2 v1 = __ldg((const float2*)(x + (size_t)(r + 8) * KD + d));
                X[p][ks][h * 2 + 0] = packh(v0.x, v0.y);
                X[p][ks][h * 2 + 1] = packh(v1.x, v1.y);
            }
        }
    }

    float res0 = 0.f, res1 = 0.f, res2 = 0.f, res3 = 0.f;

    #pragma unroll 1
    for (int k = 0; k < KK; ++k) {
        CP_WAIT(0);
        __syncthreads();

        if (k + 1 < KK) {
            uint32_t dst = smem_u32(smem4 + ((k + 1) & 1) * TILE_U4);
            const char* src = (const char*)(g_bt + (size_t)(k + 1) * TILE_BYTES);
            #pragma unroll
            for (int i = 0; i < 8; ++i) {
                int o = tid + i * 128;
                cp16(dst + o * 16, src + o * 16);
            }
            if (tid < 32) cp16(dst + (1024 + tid) * 16, src + (1024 + tid) * 16);
            CP_COMMIT();
        }

        const uint4*  abv = smem4 + (k & 1) * TILE_U4 + l;
        const float2* bv  = (const float2*)(smem4 + (k & 1) * TILE_U4 + 1024) + q;
        // 8 independent exp-sum chains (2 per output row accumulator)
        float s0a = 0.f, s0b = 0.f, s1a = 0.f, s1b = 0.f;
        float s2a = 0.f, s2b = 0.f, s3a = 0.f, s3b = 0.f;

        #pragma unroll
        for (int ch = 0; ch < 4; ++ch) {
            // bias (log2e-scaled) as initial accumulator
            float acc0[4][4], acc1[4][4];
            #pragma unroll
            for (int mt = 0; mt < 4; ++mt) {
                float2 bb = bv[(ch * 4 + mt) * 4];
                acc0[mt][0] = bb.x; acc0[mt][1] = bb.y;
                acc0[mt][2] = bb.x; acc0[mt][3] = bb.y;
                acc1[mt][0] = bb.x; acc1[mt][1] = bb.y;
                acc1[mt][2] = bb.x; acc1[mt][3] = bb.y;
            }

            // 8 LDS.128 hoisted: each uint4 = B regs for an m-tile pair
            uint4 B[4][2];
            #pragma unroll
            for (int ks = 0; ks < 4; ++ks)
                #pragma unroll
                for (int mp = 0; mp < 2; ++mp)
                    B[ks][mp] = abv[(ks * 8 + ch * 2 + mp) * 32];

            #pragma unroll
            for (int ks = 0; ks < 4; ++ks) {
                #pragma unroll
                for (int mp = 0; mp < 2; ++mp) {
                    mma16816(acc0[mp * 2 + 0], X[0][ks], B[ks][mp].x, B[ks][mp].y);
                    mma16816(acc1[mp * 2 + 0], X[1][ks], B[ks][mp].x, B[ks][mp].y);
                    mma16816(acc0[mp * 2 + 1], X[0][ks], B[ks][mp].z, B[ks][mp].w);
                    mma16816(acc1[mp * 2 + 1], X[1][ks], B[ks][mp].z, B[ks][mp].w);
                }
            }

            // fused epilogue: acc = (x@a + b)*log2e ; alternate chains by mt parity
            #pragma unroll
            for (int mt = 0; mt < 4; mt += 2) {
                s0a += ex2f(acc0[mt][0]);     s0b += ex2f(acc0[mt + 1][0]);
                s0a += ex2f(acc0[mt][1]);     s0b += ex2f(acc0[mt + 1][1]);
                s1a += ex2f(acc0[mt][2]);     s1b += ex2f(acc0[mt + 1][2]);
                s1a += ex2f(acc0[mt][3]);     s1b += ex2f(acc0[mt + 1][3]);
                s2a += ex2f(acc1[mt][0]);     s2b += ex2f(acc1[mt + 1][0]);
                s2a += ex2f(acc1[mt][1]);     s2b += ex2f(acc1[mt + 1][1]);
                s3a += ex2f(acc1[mt][2]);     s3b += ex2f(acc1[mt + 1][2]);
                s3a += ex2f(acc1[mt][3]);     s3b += ex2f(acc1[mt + 1][3]);
            }
        }

        float s0 = s0a + s0b, s1 = s1a + s1b;
        float s2 = s2a + s2b, s3 = s3a + s3b;

        s0 += __shfl_xor_sync(0xffffffffu, s0, 1);
        s0 += __shfl_xor_sync(0xffffffffu, s0, 2);
        s1 += __shfl_xor_sync(0xffffffffu, s1, 1);
        s1 += __shfl_xor_sync(0xffffffffu, s1, 2);
        s2 += __shfl_xor_sync(0xffffffffu, s2, 1);
        s2 += __shfl_xor_sync(0xffffffffu, s2, 2);
        s3 += __shfl_xor_sync(0xffffffffu, s3, 1);
        s3 += __shfl_xor_sync(0xffffffffu, s3, 2);

        float sv = g_ss[k];                 // s * ln2
        res0 = fmaf(sv, lg2f(s0), res0);
        res1 = fmaf(sv, lg2f(s1), res1);
        res2 = fmaf(sv, lg2f(s2), res2);
        res3 = fmaf(sv, lg2f(s3), res3);
    }

    if (q == 0) {
        out[row0]      = res0;
        out[row0 + 8]  = res1;
        out[row0 + 16] = res2;
        out[row0 + 24] = res3;
    }
}

extern "C" void kernel_launch(void* const* d_in, const int* in_sizes, int n_in,
                              void* d_out, int out_size)
{
    const float* x = (const float*)d_in[0];   // [131072, 64]
    const float* s = (const float*)d_in[1];   // [16]
    const float* a = (const float*)d_in[2];   // [16, 128, 64]
    const float* b = (const float*)d_in[3];   // [16, 128]
    float* out = (float*)d_out;

    cudaFuncSetAttribute(madk15, cudaFuncAttributeMaxDynamicSharedMemorySize, DYN_SMEM);

    prep<<<(65536 + KK * KM + 255) / 256, 256>>>(a, b, s);
    madk15<<<KN / BN, 128, DYN_SMEM>>>(x, out);
}

// round 17
// speedup vs baseline: 2.2238x; 1.0113x over previous
#include <cuda_runtime.h>
#include <cuda_fp16.h>
#include <cstdint>

#define KN 131072
#define KK 16
#define KM 128
#define KD 64
#define BN 128   // n-rows per CTA (4 warps x 32 rows)

#define LOG2E 1.4426950408889634f
#define LN2   0.6931471805599453f

// Per-expert tile (16896 B): [0,16384) fp16 'a' fragments (log2e-scaled),
//   one uint4 per (ks, m-tile-pair, lane); [16384,16896): bias*log2e (128 f32)
#define TILE_BYTES 16896
#define TILE_U4    (TILE_BYTES / 16)       // 1056
__device__ __align__(16) unsigned char g_bt[KK * TILE_BYTES];   // 264 KB, L2-resident
__device__ float g_ss[KK];                                      // s * ln2

// vectorized prep: one uint4 (4 output u32) per thread
__global__ void prep(const float* __restrict__ a, const float* __restrict__ b,
                     const float* __restrict__ s) {
    int t = blockIdx.x * 256 + threadIdx.x;
    if (t < 16384) {                 // 4 consecutive c-slots = one (k,ks,mp,l) uint4
        int l  = t & 31;
        int mp = (t >> 5) & 7;
        int ks = (t >> 8) & 3;
        int k  = t >> 10;
        uint32_t o[4];
        #pragma unroll
        for (int c = 0; c < 4; ++c) {
            int mt = mp * 2 + (c >> 1);
            int r  = c & 1;
            int m  = mt * 8 + (l >> 2);
            int d0 = ks * 16 + (l & 3) * 2 + r * 8;
            const float* am = a + ((size_t)k * KM + m) * KD + d0;
            __half2 h = __floats2half2_rn(am[0] * LOG2E, am[1] * LOG2E);
            o[c] = *(const uint32_t*)&h;
        }
        *(uint4*)(g_bt + (size_t)k * TILE_BYTES + ((size_t)((ks * 8 + mp) * 32 + l) << 4)) =
            make_uint4(o[0], o[1], o[2], o[3]);
    } else if (t < 16384 + KK * KM) {
        int j = t - 16384;
        int k = j >> 7, m = j & 127;
        *(float*)(g_bt + (size_t)k * TILE_BYTES + 16384 + (m << 2)) = b[j] * LOG2E;
        if (j < KK) g_ss[j] = s[j] * LN2;
    }
}

__device__ __forceinline__ void mma16816(float (&c)[4], const uint32_t (&A)[4],
                                         uint32_t b0, uint32_t b1) {
    asm volatile(
        "mma.sync.aligned.m16n8k16.row.col.f32.f16.f16.f32 "
        "{%0,%1,%2,%3}, {%4,%5,%6,%7}, {%8,%9}, {%0,%1,%2,%3};"
        : "+f"(c[0]), "+f"(c[1]), "+f"(c[2]), "+f"(c[3])
        : "r"(A[0]), "r"(A[1]), "r"(A[2]), "r"(A[3]), "r"(b0), "r"(b1));
}
__device__ __forceinline__ uint32_t smem_u32(const void* p) {
    uint32_t a;
    asm("{ .reg .u64 t; cvta.to.shared.u64 t, %1; cvt.u32.u64 %0, t; }" : "=r"(a) : "l"(p));
    return a;
}
__device__ __forceinline__ void cp16(uint32_t s, const void* g) {
    asm volatile("cp.async.cg.shared.global [%0], [%1], 16;" :: "r"(s), "l"(g));
}
#define CP_COMMIT() asm volatile("cp.async.commit_group;" ::: "memory")
#define CP_WAIT(n)  asm volatile("cp.async.wait_group %0;" :: "n"(n) : "memory")
__device__ __forceinline__ float ex2f(float v) {
    float r; asm("ex2.approx.f32 %0, %1;" : "=f"(r) : "f"(v)); return r;
}
__device__ __forceinline__ float lg2f(float v) {
    float r; asm("lg2.approx.f32 %0, %1;" : "=f"(r) : "f"(v)); return r;
}
__device__ __forceinline__ uint32_t packh(float a, float b) {
    __half2 h = __floats2half2_rn(a, b);
    return *(const uint32_t*)&h;
}
// ---- Blackwell packed fp32: two adds per instruction ----
typedef unsigned long long u64;
__device__ __forceinline__ u64 packf2(float lo, float hi) {
    u64 r; asm("mov.b64 %0, {%1, %2};" : "=l"(r) : "f"(lo), "f"(hi)); return r;
}
__device__ __forceinline__ void addf2(u64& acc, u64 v) {
    asm("add.rn.f32x2 %0, %0, %1;" : "+l"(acc) : "l"(v));
}
__device__ __forceinline__ float sumf2(u64 v) {
    float lo, hi; asm("mov.b64 {%0, %1}, %2;" : "=f"(lo), "=f"(hi) : "l"(v));
    return lo + hi;
}

#define DYN_SMEM (2 * TILE_BYTES)   // 33792 B double buffer

// madk10 structure + packed-f32x2 exp accumulation (2 adds/instr, 2 chains/row).
__global__ __launch_bounds__(128, 4)
void madk16(const float* __restrict__ x, float* __restrict__ out)
{
    extern __shared__ __align__(16) uint4 smem4[];

    const int tid = threadIdx.x;
    const int w = tid >> 5, l = tid & 31;
    const int g = l >> 2, q = l & 3;
    const int row0 = blockIdx.x * BN + w * 32 + g;

    // ---- prefetch expert 0 ----
    {
        uint32_t dst = smem_u32(smem4);
        const char* src = (const char*)g_bt;
        #pragma unroll
        for (int i = 0; i < 9; ++i) {
            int o = tid + i * 128;
            if (o < TILE_U4) cp16(dst + o * 16, src + o * 16);
        }
        CP_COMMIT();
    }

    // ---- A fragments: two 16-row fragments; reused for all experts ----
    uint32_t X[2][4][4];
    #pragma unroll
    for (int p = 0; p < 2; ++p) {
        #pragma unroll
        for (int ks = 0; ks < 4; ++ks) {
            #pragma unroll
            for (int h = 0; h < 2; ++h) {
                int d = ks * 16 + q * 2 + h * 8;
                int r = row0 + p * 16;
                float2 v0 = __ldg((const float2*)(x + (size_t)r * KD + d));
                float2 v1 = __ldg((const float2*)(x + (size_t)(r + 8) * KD + d));
                X[p][ks][h * 2 + 0] = packh(v0.x, v0.y);
                X[p][ks][h * 2 + 1] = packh(v1.x, v1.y);
            }
        }
    }

    float res0 = 0.f, res1 = 0.f, res2 = 0.f, res3 = 0.f;

    #pragma unroll 1
    for (int k = 0; k < KK; ++k) {
        CP_WAIT(0);
        __syncthreads();

        if (k + 1 < KK) {
            uint32_t dst = smem_u32(smem4 + ((k + 1) & 1) * TILE_U4);
            const char* src = (const char*)(g_bt + (size_t)(k + 1) * TILE_BYTES);
            #pragma unroll
            for (int i = 0; i < 9; ++i) {
                int o = tid + i * 128;
                if (o < TILE_U4) cp16(dst + o * 16, src + o * 16);
            }
            CP_COMMIT();
        }

        const uint4*  abv = smem4 + (k & 1) * TILE_U4 + l;
        const float2* bv  = (const float2*)(smem4 + (k & 1) * TILE_U4 + 1024) + q;
        // packed accumulators: one u64 per output row = 2 independent chains
        u64 p0 = 0ull, p1 = 0ull, p2 = 0ull, p3 = 0ull;

        #pragma unroll
        for (int ch = 0; ch < 4; ++ch) {
            // bias (log2e-scaled) as initial accumulator
            float acc0[4][4], acc1[4][4];
            #pragma unroll
            for (int mt = 0; mt < 4; ++mt) {
                float2 bb = bv[(ch * 4 + mt) * 4];
                acc0[mt][0] = bb.x; acc0[mt][1] = bb.y;
                acc0[mt][2] = bb.x; acc0[mt][3] = bb.y;
                acc1[mt][0] = bb.x; acc1[mt][1] = bb.y;
                acc1[mt][2] = bb.x; acc1[mt][3] = bb.y;
            }

            // 8 LDS.128 hoisted: each uint4 = B regs for an m-tile pair
            uint4 B[4][2];
            #pragma unroll
            for (int ks = 0; ks < 4; ++ks)
                #pragma unroll
                for (int mp = 0; mp < 2; ++mp)
                    B[ks][mp] = abv[(ks * 8 + ch * 2 + mp) * 32];

            #pragma unroll
            for (int ks = 0; ks < 4; ++ks) {
                #pragma unroll
                for (int mp = 0; mp < 2; ++mp) {
                    mma16816(acc0[mp * 2 + 0], X[0][ks], B[ks][mp].x, B[ks][mp].y);
                    mma16816(acc1[mp * 2 + 0], X[1][ks], B[ks][mp].x, B[ks][mp].y);
                    mma16816(acc0[mp * 2 + 1], X[0][ks], B[ks][mp].z, B[ks][mp].w);
                    mma16816(acc1[mp * 2 + 1], X[1][ks], B[ks][mp].z, B[ks][mp].w);
                }
            }

            // fused epilogue: pack ex2 pairs, accumulate 2-at-a-time (add.f32x2)
            #pragma unroll
            for (int mt = 0; mt < 4; ++mt) {
                addf2(p0, packf2(ex2f(acc0[mt][0]), ex2f(acc0[mt][1])));
                addf2(p1, packf2(ex2f(acc0[mt][2]), ex2f(acc0[mt][3])));
                addf2(p2, packf2(ex2f(acc1[mt][0]), ex2f(acc1[mt][1])));
                addf2(p3, packf2(ex2f(acc1[mt][2]), ex2f(acc1[mt][3])));
            }
        }

        float s0 = sumf2(p0), s1 = sumf2(p1);
        float s2 = sumf2(p2), s3 = sumf2(p3);

        s0 += __shfl_xor_sync(0xffffffffu, s0, 1);
        s0 += __shfl_xor_sync(0xffffffffu, s0, 2);
        s1 += __shfl_xor_sync(0xffffffffu, s1, 1);
        s1 += __shfl_xor_sync(0xffffffffu, s1, 2);
        s2 += __shfl_xor_sync(0xffffffffu, s2, 1);
        s2 += __shfl_xor_sync(0xffffffffu, s2, 2);
        s3 += __shfl_xor_sync(0xffffffffu, s3, 1);
        s3 += __shfl_xor_sync(0xffffffffu, s3, 2);

        float sv = g_ss[k];                 // s * ln2
        res0 = fmaf(sv, lg2f(s0), res0);
        res1 = fmaf(sv, lg2f(s1), res1);
        res2 = fmaf(sv, lg2f(s2), res2);
        res3 = fmaf(sv, lg2f(s3), res3);
    }

    if (q == 0) {
        out[row0]      = res0;
        out[row0 + 8]  = res1;
        out[row0 + 16] = res2;
        out[row0 + 24] = res3;
    }
}

extern "C" void kernel_launch(void* const* d_in, const int* in_sizes, int n_in,
                              void* d_out, int out_size)
{
    const float* x = (const float*)d_in[0];   // [131072, 64]
    const float* s = (const float*)d_in[1];   // [16]
    const float* a = (const float*)d_in[2];   // [16, 128, 64]
    const float* b = (const float*)d_in[3];   // [16, 128]
    float* out = (float*)d_out;

    cudaFuncSetAttribute(madk16, cudaFuncAttributeMaxDynamicSharedMemorySize, DYN_SMEM);

    prep<<<(16384 + KK * KM + 255) / 256, 256>>>(a, b, s);
    madk16<<<KN / BN, 128, DYN_SMEM>>>(x, out);
}